// round 1
// baseline (speedup 1.0000x reference)
#include <cuda_runtime.h>
#include <cstdint>

// DeformConv2d sampling with KS=3, PAD=1, STRIDE=1, RATIO=1 on x:(4,32,256,256) f32.
// Degenerates to an exact integer gather from the reflection-padded input:
//   out[b,c, i*3+kx, j*3+ky] = m * xp[b,c, i+kx, j+ky]
//   m = (i+kx==257 ? 2 : 1) * (j+ky==257 ? 2 : 1)     (clamp-boundary weight doubling)
//   xp[p] -> x[1] if p==0, x[254] if p==257, else x[p-1]   (reflect pad, edge excluded)
//
// One block per output row: load the single needed 256-float source row to smem,
// 192 threads write one float4 each (768 floats/row, fully coalesced).

#define H 256
#define W 256
#define OH 768
#define OW 768

__global__ __launch_bounds__(256, 8)
void deform_sample_kernel(const float* __restrict__ x, float* __restrict__ out) {
    __shared__ float row[W];

    const int orow = blockIdx.x;     // 0..767
    const int bc   = blockIdx.y;     // 0..B*C-1
    const int t    = threadIdx.x;

    // output row -> padded source row index px = i + kx
    const int i  = orow / 3;
    const int kx = orow - i * 3;
    const int px = i + kx;                 // 0..257
    const int sx = (px == 0) ? 1 : (px == H + 1) ? (H - 2) : (px - 1);
    const float mx = (px == H + 1) ? 2.0f : 1.0f;

    // load source row into smem (256 floats = 64 float4)
    const float4* src = reinterpret_cast<const float4*>(x + ((size_t)bc * H + sx) * W);
    if (t < W / 4) {
        reinterpret_cast<float4*>(row)[t] = src[t];
    }
    __syncthreads();

    if (t < OW / 4) {
        const int ocb = t * 4;
        float4 v;
        float* vp = reinterpret_cast<float*>(&v);
#pragma unroll
        for (int e = 0; e < 4; e++) {
            const int oc = ocb + e;
            const int j  = oc / 3;
            const int ky = oc - j * 3;
            const int py = j + ky;             // 0..257
            const int sy = (py == 0) ? 1 : (py == W + 1) ? (W - 2) : (py - 1);
            const float m = mx * ((py == W + 1) ? 2.0f : 1.0f);
            vp[e] = m * row[sy];
        }
        float* op = out + ((size_t)bc * OH + orow) * OW + ocb;
        *reinterpret_cast<float4*>(op) = v;
    }
}

extern "C" void kernel_launch(void* const* d_in, const int* in_sizes, int n_in,
                              void* d_out, int out_size) {
    const float* x = (const float*)d_in[0];
    float* out = (float*)d_out;

    const int bc = in_sizes[0] / (H * W);   // B*C = 128
    dim3 grid(OH, bc);
    dim3 block(256);
    deform_sample_kernel<<<grid, block>>>(x, out);
}

// round 3
// speedup vs baseline: 1.9526x; 1.9526x over previous
#include <cuda_runtime.h>
#include <cstdint>

// DeformConv2d (KS=3, PAD=1, STRIDE=1, RATIO=1) on x:(4,32,256,256) f32.
// Integer sampling positions => exact gather from reflection-padded input:
//   out[b,c, 3i+kx, 3j+ky] = m * xp[b,c, i+kx, j+ky]
//   m doubles when padded index == 257 (upper clamp corner aliasing), per axis.
//   xp[0]=x[1], xp[257]=x[254], xp[p]=x[p-1] otherwise (reflect, edge excluded).
//
// Per block: one (bc, input-row i). Build 3 fully-resolved padded rows in smem
// (reflect + boundary-x2 + row-multiplier folded in), then each thread emits
// one float4 of each of the 3 output rows via a static 3-way shuffle pattern.
// All stores are coalesced STG.128; per-element ALU is eliminated.

#define H 256
#define W 256
#define OH 768
#define OW 768
#define RPS 264   // padded smem row stride (floats); 258 used, +6 pad for OOB-safe hi vec

__global__ __launch_bounds__(192, 10)
void deform_sample_kernel(const float* __restrict__ x, float* __restrict__ out) {
    __shared__ float rp[3][RPS];

    const int i  = blockIdx.x;      // input row 0..255
    const int bc = blockIdx.y;      // 0..B*C-1
    const int t  = threadIdx.x;     // 0..191

    const float* xb = x + (size_t)bc * H * W;

    // Build 3 resolved padded rows: rp[k][py] = mx*my * x[sx][sy]
#pragma unroll
    for (int k = 0; k < 3; k++) {
        const int px = i + k;                                  // 0..257
        const int sx = (px == 0) ? 1 : (px == H + 1) ? (H - 2) : (px - 1);
        const float mx = (px == H + 1) ? 2.0f : 1.0f;
        const float* srow = xb + sx * W;
#pragma unroll
        for (int py = t; py < 258; py += 192) {
            const int sy = (py == 0) ? 1 : (py == W + 1) ? (W - 2) : (py - 1);
            const float m = mx * ((py == W + 1) ? 2.0f : 1.0f);
            rp[k][py] = m * srow[sy];
        }
    }
    __syncthreads();

    // Thread t produces output float4 index q=t of each of the 3 output rows.
    // q covers oc=4q..4q+3; with m=q/3, r=q%3 the needed padded-row elements are
    //   r=0: (a,b,c,b)  r=1: (c,d,c,d)  r=2: (e,d,e,f)
    // where a..f = rp[kx][4m .. 4m+5]  (lo = rp4[m], hi = rp4[m+1]).
    const int m = t / 3;
    const int r = t - 3 * m;

    float4* orow0 = reinterpret_cast<float4*>(out + (((size_t)bc * OH) + 3 * i) * OW);

#pragma unroll
    for (int kx = 0; kx < 3; kx++) {
        const float4* rp4 = reinterpret_cast<const float4*>(rp[kx]);
        const float4 lo = rp4[m];
        const float4 hi = rp4[m + 1];
        float4 o;
        o.x = (r == 0) ? lo.x : (r == 1) ? lo.z : hi.x;
        o.y = (r == 0) ? lo.y : lo.w;
        o.z = (r == 0) ? lo.z : (r == 1) ? lo.z : hi.x;
        o.w = (r == 0) ? lo.y : (r == 1) ? lo.w : hi.y;
        orow0[kx * (OW / 4) + t] = o;
    }
}

extern "C" void kernel_launch(void* const* d_in, const int* in_sizes, int n_in,
                              void* d_out, int out_size) {
    const float* x = (const float*)d_in[0];
    float* out = (float*)d_out;

    const int bc = in_sizes[0] / (H * W);   // B*C = 128
    dim3 grid(H, bc);
    dim3 block(192);
    deform_sample_kernel<<<grid, block>>>(x, out);
}